// round 12
// baseline (speedup 1.0000x reference)
#include <cuda_runtime.h>
#include <cstdint>

#define MAXN 100000
#define MAXE 1600000
#define D    128
#define G    64
#define REP  32
#define SCB  1024
#define TM   64      // nodes per fused-kernel block

// ---------------- device scratch ----------------
__device__ float g_h2[MAXN * D];        // pre-scaled layer-1 activation: dis_i*leaky(conv1_i)
__device__ int   g_deg[MAXN];
__device__ float g_dis[MAXN];
__device__ int   g_off[MAXN + 1];
__device__ int   g_cursor[MAXN];
__device__ int   g_adj[MAXE];           // src index
__device__ float g_wt[MAXE];            // edge norm (layer 1 only)
__device__ float g_gsum[G * REP];
__device__ int   g_bsum[128];
__device__ int   g_bbase[128];
__device__ int   g_is64;

// ---------------- dtype-agnostic index read ----------------
__device__ __forceinline__ int idx_at(const void* p, size_t i) {
    if (g_is64) return (int)((const long long*)p)[i];
    return ((const int*)p)[i];
}

// ---------------- init (+dtype detect) ----------------
__global__ void k_init(const int* __restrict__ ei32, int n) {
    int i = blockIdx.x * blockDim.x + threadIdx.x;
    if (i == 0) {
        int allz = 1;
        for (int j = 1; j < 32; j += 2)
            if (ei32[j] != 0) allz = 0;
        g_is64 = allz;
    }
    if (i < n) g_deg[i] = 1;
    if (i < G * REP) g_gsum[i] = 0.f;
}

// ---------------- in-degree count ----------------
__global__ void k_deg(const void* __restrict__ ei, int e) {
    int i = blockIdx.x * blockDim.x + threadIdx.x;
    if (i < e) atomicAdd(&g_deg[idx_at(ei, (size_t)e + i)], 1);
}

// ---------------- scan phase 1: block sums of (deg-1); also dis=rsqrt(deg) ----------------
__global__ void k_scan1(int n) {
    int i = blockIdx.x * SCB + threadIdx.x;
    int v = 0;
    if (i < n) {
        int d = g_deg[i];
        g_dis[i] = rsqrtf((float)d);
        v = d - 1;
    }
    int s = v;
#pragma unroll
    for (int o = 16; o; o >>= 1) s += __shfl_down_sync(0xffffffffu, s, o);
    __shared__ int ws[SCB / 32];
    int w = threadIdx.x >> 5, l = threadIdx.x & 31;
    if (l == 0) ws[w] = s;
    __syncthreads();
    if (w == 0) {
        int t = (l < SCB / 32) ? ws[l] : 0;
#pragma unroll
        for (int o = 16; o; o >>= 1) t += __shfl_down_sync(0xffffffffu, t, o);
        if (l == 0) g_bsum[blockIdx.x] = t;
    }
}

// ---------------- scan phase 2 ----------------
__global__ void k_scan2(int nb, int n) {
    __shared__ int sm[128];
    int t = threadIdx.x;
    int v = (t < nb) ? g_bsum[t] : 0;
    sm[t] = v;
    __syncthreads();
    for (int o = 1; o < 128; o <<= 1) {
        int u = (t >= o) ? sm[t - o] : 0;
        __syncthreads();
        if (t >= o) sm[t] += u;
        __syncthreads();
    }
    g_bbase[t] = sm[t] - v;
    if (t == 127) g_off[n] = sm[127];
}

// ---------------- scan phase 3 (seeds cursor = off) ----------------
__global__ void k_scan3(int n) {
    int i = blockIdx.x * SCB + threadIdx.x;
    int v = (i < n) ? (g_deg[i] - 1) : 0;
    int incl = v;
#pragma unroll
    for (int o = 1; o < 32; o <<= 1) {
        int u = __shfl_up_sync(0xffffffffu, incl, o);
        if ((threadIdx.x & 31) >= o) incl += u;
    }
    __shared__ int ws[SCB / 32];
    int w = threadIdx.x >> 5, l = threadIdx.x & 31;
    if (l == 31) ws[w] = incl;
    __syncthreads();
    if (w == 0) {
        int s = (l < SCB / 32) ? ws[l] : 0;
        int si = s;
#pragma unroll
        for (int o = 1; o < 32; o <<= 1) {
            int u = __shfl_up_sync(0xffffffffu, si, o);
            if (l >= o) si += u;
        }
        ws[l] = si - s;
    }
    __syncthreads();
    if (i < n) {
        int off = g_bbase[blockIdx.x] + ws[w] + (incl - v);
        g_off[i] = off;
        g_cursor[i] = off;
    }
}

// ---------------- fill CSR (split arrays) ----------------
__global__ void k_fill(const void* __restrict__ ei, int e) {
    int i = blockIdx.x * blockDim.x + threadIdx.x;
    if (i < e) {
        int r = idx_at(ei, i);
        int c = idx_at(ei, (size_t)e + i);
        int pos = atomicAdd(&g_cursor[c], 1);
        g_adj[pos] = r;
        g_wt[pos] = g_dis[r] * g_dis[c];
    }
}

// ---------------- fused layer: gather -> smem -> barrier-free FFMA GEMM -> epilogue ----------------
__device__ __forceinline__ float leaky(float x) { return x >= 0.f ? x : 0.01f * x; }

template <int POOL, int WEIGHTED>
__global__ __launch_bounds__(256, 3) void k_fused(
    const float4* __restrict__ in, const float* __restrict__ W,
    const float* __restrict__ bias, const float* __restrict__ fcW,
    const void* __restrict__ batch, float4* __restrict__ hout, int n)
{
    __shared__ float At[D][66];     // feature-major agg tile: At[feature][node]
    __shared__ float rowsum[TM];

    int tid = threadIdx.x;
    int warp = tid >> 5, lane = tid & 31;
    int row0 = blockIdx.x * TM;

    // ---- phase 1: gather (warp per node, lane = feature quad), 4-wide MLP ----
    for (int nd = warp; nd < TM; nd += 8) {
        int node = row0 + nd;
        float4 acc = make_float4(0.f, 0.f, 0.f, 0.f);
        if (node < n) {
            float di = g_dis[node];
            float4 v = in[(size_t)node * 32 + lane];
            if (WEIGHTED) {
                float self = di * di;
                acc.x = v.x * self; acc.y = v.y * self;
                acc.z = v.z * self; acc.w = v.w * self;
            } else {
                acc = v;            // pre-scaled input: plain sum
            }
            int s = g_off[node], e = g_off[node + 1];
            int j = s;
            for (; j + 4 <= e; j += 4) {
                int s0 = g_adj[j], s1 = g_adj[j + 1], s2 = g_adj[j + 2], s3 = g_adj[j + 3];
                float4 v0 = in[(size_t)s0 * 32 + lane];
                float4 v1 = in[(size_t)s1 * 32 + lane];
                float4 v2 = in[(size_t)s2 * 32 + lane];
                float4 v3 = in[(size_t)s3 * 32 + lane];
                if (WEIGHTED) {
                    float w0 = g_wt[j], w1 = g_wt[j + 1], w2 = g_wt[j + 2], w3 = g_wt[j + 3];
                    acc.x += v0.x * w0 + v1.x * w1 + v2.x * w2 + v3.x * w3;
                    acc.y += v0.y * w0 + v1.y * w1 + v2.y * w2 + v3.y * w3;
                    acc.z += v0.z * w0 + v1.z * w1 + v2.z * w2 + v3.z * w3;
                    acc.w += v0.w * w0 + v1.w * w1 + v2.w * w2 + v3.w * w3;
                } else {
                    acc.x += v0.x + v1.x + v2.x + v3.x;
                    acc.y += v0.y + v1.y + v2.y + v3.y;
                    acc.z += v0.z + v1.z + v2.z + v3.z;
                    acc.w += v0.w + v1.w + v2.w + v3.w;
                }
            }
            for (; j < e; j++) {
                int s0 = g_adj[j];
                float4 v0 = in[(size_t)s0 * 32 + lane];
                if (WEIGHTED) {
                    float w0 = g_wt[j];
                    acc.x += v0.x * w0; acc.y += v0.y * w0;
                    acc.z += v0.z * w0; acc.w += v0.w * w0;
                } else {
                    acc.x += v0.x; acc.y += v0.y; acc.z += v0.z; acc.w += v0.w;
                }
            }
            if (!WEIGHTED) {
                acc.x *= di; acc.y *= di; acc.z *= di; acc.w *= di;
            }
        }
        int c = lane * 4;
        At[c + 0][nd] = acc.x;
        At[c + 1][nd] = acc.y;
        At[c + 2][nd] = acc.z;
        At[c + 3][nd] = acc.w;
    }
    if (POOL && tid < TM) rowsum[tid] = 0.f;
    __syncthreads();                // the ONLY block barrier before epilogue

    // ---- phase 2: GEMM C[64x128] = At^T @ W, W streamed from L1 (no smem, no barriers) ----
    int tx = tid & 15;              // rows tx*4 .. tx*4+3
    int ty = tid >> 4;              // cols ty*8 .. ty*8+7
    const float4* Wc0 = (const float4*)&W[ty * 8];
    const float4* Wc1 = (const float4*)&W[ty * 8 + 4];
    float acc[4][8];
#pragma unroll
    for (int r = 0; r < 4; r++)
#pragma unroll
        for (int j = 0; j < 8; j++) acc[r][j] = 0.f;

#pragma unroll 8
    for (int k = 0; k < D; k++) {
        float a[4], b[8];
#pragma unroll
        for (int r = 0; r < 4; r++) a[r] = At[k][tx * 4 + r];
        *(float4*)&b[0] = __ldg(&Wc0[k * 32]);
        *(float4*)&b[4] = __ldg(&Wc1[k * 32]);
#pragma unroll
        for (int r = 0; r < 4; r++)
#pragma unroll
            for (int j = 0; j < 8; j++) acc[r][j] += a[r] * b[j];
    }

    // ---- phase 3: epilogue ----
    if (!POOL) {
#pragma unroll
        for (int r = 0; r < 4; r++) {
            int row = row0 + tx * 4 + r;
            if (row < n) {
                float dr = g_dis[row];
                float4 o0, o1;
                o0.x = dr * leaky(acc[r][0] + bias[ty * 8 + 0]);
                o0.y = dr * leaky(acc[r][1] + bias[ty * 8 + 1]);
                o0.z = dr * leaky(acc[r][2] + bias[ty * 8 + 2]);
                o0.w = dr * leaky(acc[r][3] + bias[ty * 8 + 3]);
                o1.x = dr * leaky(acc[r][4] + bias[ty * 8 + 4]);
                o1.y = dr * leaky(acc[r][5] + bias[ty * 8 + 5]);
                o1.z = dr * leaky(acc[r][6] + bias[ty * 8 + 6]);
                o1.w = dr * leaky(acc[r][7] + bias[ty * 8 + 7]);
                hout[(size_t)row * 32 + ty * 2] = o0;
                hout[(size_t)row * 32 + ty * 2 + 1] = o1;
            }
        }
    } else {
        float fj[8], bj[8];
#pragma unroll
        for (int j = 0; j < 8; j++) { fj[j] = fcW[ty * 8 + j]; bj[j] = bias[ty * 8 + j]; }
#pragma unroll
        for (int r = 0; r < 4; r++) {
            float s = 0.f;
#pragma unroll
            for (int j = 0; j < 8; j++) s += leaky(acc[r][j] + bj[j]) * fj[j];
            atomicAdd(&rowsum[tx * 4 + r], s);
        }
        __syncthreads();
        if (tid < TM) {
            int row = row0 + tid;
            if (row < n) {
                int g = idx_at(batch, row);
                atomicAdd(&g_gsum[g * REP + (blockIdx.x & (REP - 1))], rowsum[tid]);
            }
        }
    }
}

// ---------------- final ----------------
__global__ void k_final(const void* __restrict__ batch, const float* __restrict__ fcb,
                        float* __restrict__ out, int n) {
    __shared__ int lb[G + 1];
    int t = threadIdx.x;
    if (t <= G) {
        int lo = 0, hi = n;
        while (lo < hi) {
            int mid = (lo + hi) >> 1;
            if (idx_at(batch, mid) < t) lo = mid + 1; else hi = mid;
        }
        lb[t] = lo;
    }
    __syncthreads();
    if (t < G) {
        float s = 0.f;
#pragma unroll
        for (int r = 0; r < REP; r++) s += g_gsum[t * REP + r];
        float c = (float)(lb[t + 1] - lb[t]);
        if (c < 1.f) c = 1.f;
        out[t] = s / c + fcb[0];
    }
}

// ---------------- launch ----------------
extern "C" void kernel_launch(void* const* d_in, const int* in_sizes, int n_in,
                              void* d_out, int out_size) {
    const float* x    = (const float*)d_in[0];
    const void*  ei   = d_in[1];
    const void*  bat  = d_in[2];
    const float* W1   = (const float*)d_in[3];
    const float* b1   = (const float*)d_in[4];
    const float* W2   = (const float*)d_in[5];
    const float* b2   = (const float*)d_in[6];
    const float* fcW  = (const float*)d_in[7];
    const float* fcb  = (const float*)d_in[8];
    float*       out  = (float*)d_out;

    int n = in_sizes[0] / D;
    int e = in_sizes[1] / 2;
    int nb = (n + SCB - 1) / SCB;

    float* h2;
    cudaGetSymbolAddress((void**)&h2, g_h2);

    int tb = 256;
    // CSR build
    k_init<<<(n + tb - 1) / tb, tb>>>((const int*)ei, n);
    k_deg<<<(e + tb - 1) / tb, tb>>>(ei, e);
    k_scan1<<<nb, SCB>>>(n);
    k_scan2<<<1, 128>>>(nb, n);
    k_scan3<<<nb, SCB>>>(n);
    k_fill<<<(e + tb - 1) / tb, tb>>>(ei, e);

    int gblk = (n + TM - 1) / TM;
    // layer 1: h2 = dis .* leaky(agg(x)@W1 + b1)   (weighted gather)
    k_fused<0, 1><<<gblk, 256>>>((const float4*)x, W1, b1, nullptr, nullptr,
                                 (float4*)h2, n);
    // layer 2 + pool/fc (pure-sum gather over pre-scaled h2)
    k_fused<1, 0><<<gblk, 256>>>((const float4*)h2, W2, b2, fcW, bat, nullptr, n);

    k_final<<<1, 128>>>(bat, fcb, out, n);
}

// round 13
// speedup vs baseline: 1.1082x; 1.1082x over previous
#include <cuda_runtime.h>
#include <cstdint>

#define MAXN 100000
#define MAXE 1600000
#define D    128
#define G    64
#define REP  32
#define SCB  1024
#define TM   64      // nodes per fused-kernel block

// ---------------- device scratch ----------------
__device__ float g_h2[MAXN * D];        // pre-scaled layer-1 activation: dis_i*leaky(conv1_i)
__device__ int   g_deg[MAXN];
__device__ float g_dis[MAXN];
__device__ int   g_off[MAXN + 1];
__device__ int   g_cursor[MAXN];
__device__ int   g_adj[MAXE];           // src index
__device__ float g_wt[MAXE];            // edge norm (layer 1 only)
__device__ float g_gsum[G * REP];
__device__ int   g_bsum[128];
__device__ int   g_bbase[128];
__device__ int   g_is64;

// ---------------- dtype-agnostic index read ----------------
__device__ __forceinline__ int idx_at(const void* p, size_t i) {
    if (g_is64) return (int)((const long long*)p)[i];
    return ((const int*)p)[i];
}

// ---------------- init (+dtype detect) ----------------
__global__ void k_init(const int* __restrict__ ei32, int n) {
    int i = blockIdx.x * blockDim.x + threadIdx.x;
    if (i == 0) {
        int allz = 1;
        for (int j = 1; j < 32; j += 2)
            if (ei32[j] != 0) allz = 0;
        g_is64 = allz;
    }
    if (i < n) g_deg[i] = 1;
    if (i < G * REP) g_gsum[i] = 0.f;
}

// ---------------- in-degree count ----------------
__global__ void k_deg(const void* __restrict__ ei, int e) {
    int i = blockIdx.x * blockDim.x + threadIdx.x;
    if (i < e) atomicAdd(&g_deg[idx_at(ei, (size_t)e + i)], 1);
}

// ---------------- scan phase 1: block sums of (deg-1); also dis=rsqrt(deg) ----------------
__global__ void k_scan1(int n) {
    int i = blockIdx.x * SCB + threadIdx.x;
    int v = 0;
    if (i < n) {
        int d = g_deg[i];
        g_dis[i] = rsqrtf((float)d);
        v = d - 1;
    }
    int s = v;
#pragma unroll
    for (int o = 16; o; o >>= 1) s += __shfl_down_sync(0xffffffffu, s, o);
    __shared__ int ws[SCB / 32];
    int w = threadIdx.x >> 5, l = threadIdx.x & 31;
    if (l == 0) ws[w] = s;
    __syncthreads();
    if (w == 0) {
        int t = (l < SCB / 32) ? ws[l] : 0;
#pragma unroll
        for (int o = 16; o; o >>= 1) t += __shfl_down_sync(0xffffffffu, t, o);
        if (l == 0) g_bsum[blockIdx.x] = t;
    }
}

// ---------------- scan phase 2 ----------------
__global__ void k_scan2(int nb, int n) {
    __shared__ int sm[128];
    int t = threadIdx.x;
    int v = (t < nb) ? g_bsum[t] : 0;
    sm[t] = v;
    __syncthreads();
    for (int o = 1; o < 128; o <<= 1) {
        int u = (t >= o) ? sm[t - o] : 0;
        __syncthreads();
        if (t >= o) sm[t] += u;
        __syncthreads();
    }
    g_bbase[t] = sm[t] - v;
    if (t == 127) g_off[n] = sm[127];
}

// ---------------- scan phase 3 (seeds cursor = off) ----------------
__global__ void k_scan3(int n) {
    int i = blockIdx.x * SCB + threadIdx.x;
    int v = (i < n) ? (g_deg[i] - 1) : 0;
    int incl = v;
#pragma unroll
    for (int o = 1; o < 32; o <<= 1) {
        int u = __shfl_up_sync(0xffffffffu, incl, o);
        if ((threadIdx.x & 31) >= o) incl += u;
    }
    __shared__ int ws[SCB / 32];
    int w = threadIdx.x >> 5, l = threadIdx.x & 31;
    if (l == 31) ws[w] = incl;
    __syncthreads();
    if (w == 0) {
        int s = (l < SCB / 32) ? ws[l] : 0;
        int si = s;
#pragma unroll
        for (int o = 1; o < 32; o <<= 1) {
            int u = __shfl_up_sync(0xffffffffu, si, o);
            if (l >= o) si += u;
        }
        ws[l] = si - s;
    }
    __syncthreads();
    if (i < n) {
        int off = g_bbase[blockIdx.x] + ws[w] + (incl - v);
        g_off[i] = off;
        g_cursor[i] = off;
    }
}

// ---------------- fill CSR (split arrays) ----------------
__global__ void k_fill(const void* __restrict__ ei, int e) {
    int i = blockIdx.x * blockDim.x + threadIdx.x;
    if (i < e) {
        int r = idx_at(ei, i);
        int c = idx_at(ei, (size_t)e + i);
        int pos = atomicAdd(&g_cursor[c], 1);
        g_adj[pos] = r;
        g_wt[pos] = g_dis[r] * g_dis[c];
    }
}

// ---------------- fused layer: gather -> smem -> smem-staged FFMA GEMM -> epilogue ----------------
__device__ __forceinline__ float leaky(float x) { return x >= 0.f ? x : 0.01f * x; }

template <int POOL, int WEIGHTED>
__global__ __launch_bounds__(256, 4) void k_fused(
    const float4* __restrict__ in, const float* __restrict__ W,
    const float* __restrict__ bias, const float* __restrict__ fcW,
    const void* __restrict__ batch, float4* __restrict__ hout, int n)
{
    __shared__ float At[D][66];     // feature-major agg tile: At[feature][node]
    __shared__ float Ws[16][D];
    __shared__ float rowsum[TM];

    int tid = threadIdx.x;
    int warp = tid >> 5, lane = tid & 31;
    int row0 = blockIdx.x * TM;

    // ---- phase 1: gather (warp per node, lane = feature quad), 4-wide MLP ----
    for (int nd = warp; nd < TM; nd += 8) {
        int node = row0 + nd;
        float4 acc = make_float4(0.f, 0.f, 0.f, 0.f);
        if (node < n) {
            float di = g_dis[node];
            float4 v = in[(size_t)node * 32 + lane];
            if (WEIGHTED) {
                float self = di * di;
                acc.x = v.x * self; acc.y = v.y * self;
                acc.z = v.z * self; acc.w = v.w * self;
            } else {
                acc = v;            // pre-scaled input: plain sum
            }
            int s = g_off[node], e = g_off[node + 1];
            int j = s;
            for (; j + 4 <= e; j += 4) {
                int s0 = g_adj[j], s1 = g_adj[j + 1], s2 = g_adj[j + 2], s3 = g_adj[j + 3];
                float4 v0 = in[(size_t)s0 * 32 + lane];
                float4 v1 = in[(size_t)s1 * 32 + lane];
                float4 v2 = in[(size_t)s2 * 32 + lane];
                float4 v3 = in[(size_t)s3 * 32 + lane];
                if (WEIGHTED) {
                    float w0 = g_wt[j], w1 = g_wt[j + 1], w2 = g_wt[j + 2], w3 = g_wt[j + 3];
                    acc.x += v0.x * w0 + v1.x * w1 + v2.x * w2 + v3.x * w3;
                    acc.y += v0.y * w0 + v1.y * w1 + v2.y * w2 + v3.y * w3;
                    acc.z += v0.z * w0 + v1.z * w1 + v2.z * w2 + v3.z * w3;
                    acc.w += v0.w * w0 + v1.w * w1 + v2.w * w2 + v3.w * w3;
                } else {
                    acc.x += v0.x + v1.x + v2.x + v3.x;
                    acc.y += v0.y + v1.y + v2.y + v3.y;
                    acc.z += v0.z + v1.z + v2.z + v3.z;
                    acc.w += v0.w + v1.w + v2.w + v3.w;
                }
            }
            for (; j < e; j++) {
                int s0 = g_adj[j];
                float4 v0 = in[(size_t)s0 * 32 + lane];
                if (WEIGHTED) {
                    float w0 = g_wt[j];
                    acc.x += v0.x * w0; acc.y += v0.y * w0;
                    acc.z += v0.z * w0; acc.w += v0.w * w0;
                } else {
                    acc.x += v0.x; acc.y += v0.y; acc.z += v0.z; acc.w += v0.w;
                }
            }
            if (!WEIGHTED) {
                acc.x *= di; acc.y *= di; acc.z *= di; acc.w *= di;
            }
        }
        int c = lane * 4;
        At[c + 0][nd] = acc.x;
        At[c + 1][nd] = acc.y;
        At[c + 2][nd] = acc.z;
        At[c + 3][nd] = acc.w;
    }
    if (POOL && tid < TM) rowsum[tid] = 0.f;

    // ---- phase 2: GEMM C[64x128] = At^T @ W, W staged in smem slabs ----
    int tx = tid & 15;              // rows tx*4 .. tx*4+3
    int ty = tid >> 4;              // cols ty*8 .. ty*8+7
    float acc[4][8];
#pragma unroll
    for (int r = 0; r < 4; r++)
#pragma unroll
        for (int j = 0; j < 8; j++) acc[r][j] = 0.f;

    for (int kb = 0; kb < D; kb += 16) {
#pragma unroll
        for (int l = 0; l < 2; l++) {
            int idx4 = tid + l * 256;
            int k = idx4 >> 5, c4 = idx4 & 31;
            *(float4*)&Ws[k][c4 * 4] = *(const float4*)&W[(size_t)(kb + k) * D + c4 * 4];
        }
        __syncthreads();
#pragma unroll
        for (int k = 0; k < 16; k++) {
            float a[4], b[8];
#pragma unroll
            for (int r = 0; r < 4; r++) a[r] = At[kb + k][tx * 4 + r];
            *(float4*)&b[0] = *(float4*)&Ws[k][ty * 8];
            *(float4*)&b[4] = *(float4*)&Ws[k][ty * 8 + 4];
#pragma unroll
            for (int r = 0; r < 4; r++)
#pragma unroll
                for (int j = 0; j < 8; j++) acc[r][j] += a[r] * b[j];
        }
        __syncthreads();
    }

    // ---- phase 3: epilogue ----
    if (!POOL) {
#pragma unroll
        for (int r = 0; r < 4; r++) {
            int row = row0 + tx * 4 + r;
            if (row < n) {
                float dr = g_dis[row];
                float4 o0, o1;
                o0.x = dr * leaky(acc[r][0] + bias[ty * 8 + 0]);
                o0.y = dr * leaky(acc[r][1] + bias[ty * 8 + 1]);
                o0.z = dr * leaky(acc[r][2] + bias[ty * 8 + 2]);
                o0.w = dr * leaky(acc[r][3] + bias[ty * 8 + 3]);
                o1.x = dr * leaky(acc[r][4] + bias[ty * 8 + 4]);
                o1.y = dr * leaky(acc[r][5] + bias[ty * 8 + 5]);
                o1.z = dr * leaky(acc[r][6] + bias[ty * 8 + 6]);
                o1.w = dr * leaky(acc[r][7] + bias[ty * 8 + 7]);
                hout[(size_t)row * 32 + ty * 2] = o0;
                hout[(size_t)row * 32 + ty * 2 + 1] = o1;
            }
        }
    } else {
        float fj[8], bj[8];
#pragma unroll
        for (int j = 0; j < 8; j++) { fj[j] = fcW[ty * 8 + j]; bj[j] = bias[ty * 8 + j]; }
#pragma unroll
        for (int r = 0; r < 4; r++) {
            float s = 0.f;
#pragma unroll
            for (int j = 0; j < 8; j++) s += leaky(acc[r][j] + bj[j]) * fj[j];
            atomicAdd(&rowsum[tx * 4 + r], s);
        }
        __syncthreads();
        if (tid < TM) {
            int row = row0 + tid;
            if (row < n) {
                int g = idx_at(batch, row);
                atomicAdd(&g_gsum[g * REP + (blockIdx.x & (REP - 1))], rowsum[tid]);
            }
        }
    }
}

// ---------------- final ----------------
__global__ void k_final(const void* __restrict__ batch, const float* __restrict__ fcb,
                        float* __restrict__ out, int n) {
    __shared__ int lb[G + 1];
    int t = threadIdx.x;
    if (t <= G) {
        int lo = 0, hi = n;
        while (lo < hi) {
            int mid = (lo + hi) >> 1;
            if (idx_at(batch, mid) < t) lo = mid + 1; else hi = mid;
        }
        lb[t] = lo;
    }
    __syncthreads();
    if (t < G) {
        float s = 0.f;
#pragma unroll
        for (int r = 0; r < REP; r++) s += g_gsum[t * REP + r];
        float c = (float)(lb[t + 1] - lb[t]);
        if (c < 1.f) c = 1.f;
        out[t] = s / c + fcb[0];
    }
}

// ---------------- launch ----------------
extern "C" void kernel_launch(void* const* d_in, const int* in_sizes, int n_in,
                              void* d_out, int out_size) {
    const float* x    = (const float*)d_in[0];
    const void*  ei   = d_in[1];
    const void*  bat  = d_in[2];
    const float* W1   = (const float*)d_in[3];
    const float* b1   = (const float*)d_in[4];
    const float* W2   = (const float*)d_in[5];
    const float* b2   = (const float*)d_in[6];
    const float* fcW  = (const float*)d_in[7];
    const float* fcb  = (const float*)d_in[8];
    float*       out  = (float*)d_out;

    int n = in_sizes[0] / D;
    int e = in_sizes[1] / 2;
    int nb = (n + SCB - 1) / SCB;

    float* h2;
    cudaGetSymbolAddress((void**)&h2, g_h2);

    int tb = 256;
    // CSR build
    k_init<<<(n + tb - 1) / tb, tb>>>((const int*)ei, n);
    k_deg<<<(e + tb - 1) / tb, tb>>>(ei, e);
    k_scan1<<<nb, SCB>>>(n);
    k_scan2<<<1, 128>>>(nb, n);
    k_scan3<<<nb, SCB>>>(n);
    k_fill<<<(e + tb - 1) / tb, tb>>>(ei, e);

    int gblk = (n + TM - 1) / TM;
    // layer 1: h2 = dis .* leaky(agg(x)@W1 + b1)   (weighted gather)
    k_fused<0, 1><<<gblk, 256>>>((const float4*)x, W1, b1, nullptr, nullptr,
                                 (float4*)h2, n);
    // layer 2 + pool/fc (pure-sum gather over pre-scaled h2)
    k_fused<1, 0><<<gblk, 256>>>((const float4*)h2, W2, b2, fcW, bat, nullptr, n);

    k_final<<<1, 128>>>(bat, fcb, out, n);
}

// round 14
// speedup vs baseline: 1.1421x; 1.0306x over previous
#include <cuda_runtime.h>
#include <cuda_fp16.h>
#include <cstdint>

#define MAXN 100000
#define MAXE 1600000
#define D    128
#define G    64
#define REP  32
#define SCB  1024
#define TM   64      // nodes per fused-kernel block

// ---------------- device scratch ----------------
__device__ __half g_h2[MAXN * D];       // fp16 pre-scaled layer-1 activation
__device__ int   g_deg[MAXN];           // in-degree (memset to 0)
__device__ float g_dis[MAXN];
__device__ int   g_off[MAXN + 1];
__device__ int   g_cursor[MAXN];
__device__ int   g_adj[MAXE];           // src index
__device__ float g_wt[MAXE];            // edge norm (layer 1 only)
__device__ float g_gsum[G * REP];       // memset to 0
__device__ int   g_bsum[128];
__device__ int   g_is64;

// ---------------- dtype-agnostic index read ----------------
__device__ __forceinline__ int idx_at(const void* p, size_t i, int is64) {
    if (is64) return (int)((const long long*)p)[i];
    return ((const int*)p)[i];
}

__device__ __forceinline__ int detect64(const int* w) {
    int allz = 1;
    for (int j = 1; j < 32; j += 2)
        if (w[j] != 0) allz = 0;
    return allz;
}

// ---------------- in-degree count (per-block dtype detect) ----------------
__global__ void k_deg(const void* __restrict__ ei, int e) {
    __shared__ int s64;
    if (threadIdx.x == 0) s64 = detect64((const int*)ei);
    __syncthreads();
    int i = blockIdx.x * blockDim.x + threadIdx.x;
    if (i < e) atomicAdd(&g_deg[idx_at(ei, (size_t)e + i, s64)], 1);
}

// ---------------- scanA: block sums of deg; dis=rsqrt(deg+1); publish g_is64 ----------------
__global__ void k_scanA(const int* __restrict__ ei32, int n) {
    if (blockIdx.x == 0 && threadIdx.x == 0) g_is64 = detect64(ei32);
    int i = blockIdx.x * SCB + threadIdx.x;
    int v = 0;
    if (i < n) {
        int d = g_deg[i];
        g_dis[i] = rsqrtf((float)(d + 1));
        v = d;
    }
    int s = v;
#pragma unroll
    for (int o = 16; o; o >>= 1) s += __shfl_down_sync(0xffffffffu, s, o);
    __shared__ int ws[SCB / 32];
    int w = threadIdx.x >> 5, l = threadIdx.x & 31;
    if (l == 0) ws[w] = s;
    __syncthreads();
    if (w == 0) {
        int t = (l < SCB / 32) ? ws[l] : 0;
#pragma unroll
        for (int o = 16; o; o >>= 1) t += __shfl_down_sync(0xffffffffu, t, o);
        if (l == 0) g_bsum[blockIdx.x] = t;
    }
}

// ---------------- scanB: redundant block-sum scan + per-element offsets + cursor ----------------
__global__ void k_scanB(int nb, int n) {
    __shared__ int sm[128];
    __shared__ int ws[SCB / 32];
    int t = threadIdx.x;
    if (t < 128) sm[t] = (t < nb) ? g_bsum[t] : 0;
    __syncthreads();
    for (int o = 1; o < 128; o <<= 1) {
        int u = (t >= o && t < 128) ? sm[t - o] : 0;
        __syncthreads();
        if (t >= o && t < 128) sm[t] += u;
        __syncthreads();
    }
    int bbase = sm[blockIdx.x] - g_bsum[blockIdx.x];   // exclusive prefix of my block
    if (blockIdx.x == 0 && t == 0) g_off[n] = sm[127];

    int i = blockIdx.x * SCB + t;
    int v = (i < n) ? g_deg[i] : 0;
    int incl = v;
#pragma unroll
    for (int o = 1; o < 32; o <<= 1) {
        int u = __shfl_up_sync(0xffffffffu, incl, o);
        if ((t & 31) >= o) incl += u;
    }
    int w = t >> 5, l = t & 31;
    if (l == 31) ws[w] = incl;
    __syncthreads();
    if (w == 0) {
        int s = (l < SCB / 32) ? ws[l] : 0;
        int si = s;
#pragma unroll
        for (int o = 1; o < 32; o <<= 1) {
            int u = __shfl_up_sync(0xffffffffu, si, o);
            if (l >= o) si += u;
        }
        ws[l] = si - s;
    }
    __syncthreads();
    if (i < n) {
        int off = bbase + ws[w] + (incl - v);
        g_off[i] = off;
        g_cursor[i] = off;
    }
}

// ---------------- fill CSR (split arrays) ----------------
__global__ void k_fill(const void* __restrict__ ei, int e) {
    int is64 = g_is64;
    int i = blockIdx.x * blockDim.x + threadIdx.x;
    if (i < e) {
        int r = idx_at(ei, i, is64);
        int c = idx_at(ei, (size_t)e + i, is64);
        int pos = atomicAdd(&g_cursor[c], 1);
        g_adj[pos] = r;
        g_wt[pos] = g_dis[r] * g_dis[c];
    }
}

// ---------------- fused layer: gather -> smem -> smem-staged FFMA GEMM -> epilogue ----------------
__device__ __forceinline__ float leaky(float x) { return x >= 0.f ? x : 0.01f * x; }

template <int POOL, int WEIGHTED>
__global__ __launch_bounds__(256, 4) void k_fused(
    const void* __restrict__ in, const float* __restrict__ W,
    const float* __restrict__ bias, const float* __restrict__ fcW,
    const void* __restrict__ batch, void* __restrict__ hout, int n)
{
    __shared__ float At[D][66];     // feature-major agg tile: At[feature][node]
    __shared__ float Ws[16][D];
    __shared__ float rowsum[TM];

    int tid = threadIdx.x;
    int warp = tid >> 5, lane = tid & 31;
    int row0 = blockIdx.x * TM;

    const float4* inf = (const float4*)in;      // WEIGHTED (layer 1): fp32 input
    const uint2*  inh = (const uint2*)in;       // !WEIGHTED (layer 2): fp16 input

    // ---- phase 1: gather (warp per node, lane = feature quad), 4-wide MLP ----
    for (int nd = warp; nd < TM; nd += 8) {
        int node = row0 + nd;
        float4 acc = make_float4(0.f, 0.f, 0.f, 0.f);
        if (node < n) {
            float di = g_dis[node];
            int s = g_off[node], e = g_off[node + 1];
            int j = s;
            if (WEIGHTED) {
                float self = di * di;
                float4 v = inf[(size_t)node * 32 + lane];
                acc.x = v.x * self; acc.y = v.y * self;
                acc.z = v.z * self; acc.w = v.w * self;
                for (; j + 4 <= e; j += 4) {
                    int s0 = g_adj[j], s1 = g_adj[j + 1], s2 = g_adj[j + 2], s3 = g_adj[j + 3];
                    float4 v0 = inf[(size_t)s0 * 32 + lane];
                    float4 v1 = inf[(size_t)s1 * 32 + lane];
                    float4 v2 = inf[(size_t)s2 * 32 + lane];
                    float4 v3 = inf[(size_t)s3 * 32 + lane];
                    float w0 = g_wt[j], w1 = g_wt[j + 1], w2 = g_wt[j + 2], w3 = g_wt[j + 3];
                    acc.x += v0.x * w0 + v1.x * w1 + v2.x * w2 + v3.x * w3;
                    acc.y += v0.y * w0 + v1.y * w1 + v2.y * w2 + v3.y * w3;
                    acc.z += v0.z * w0 + v1.z * w1 + v2.z * w2 + v3.z * w3;
                    acc.w += v0.w * w0 + v1.w * w1 + v2.w * w2 + v3.w * w3;
                }
                for (; j < e; j++) {
                    int s0 = g_adj[j];
                    float w0 = g_wt[j];
                    float4 v0 = inf[(size_t)s0 * 32 + lane];
                    acc.x += v0.x * w0; acc.y += v0.y * w0;
                    acc.z += v0.z * w0; acc.w += v0.w * w0;
                }
            } else {
                uint2 u = inh[(size_t)node * 32 + lane];
                float2 f0 = __half22float2(*(const __half2*)&u.x);
                float2 f1 = __half22float2(*(const __half2*)&u.y);
                acc.x = f0.x; acc.y = f0.y; acc.z = f1.x; acc.w = f1.y;
                for (; j + 4 <= e; j += 4) {
                    int s0 = g_adj[j], s1 = g_adj[j + 1], s2 = g_adj[j + 2], s3 = g_adj[j + 3];
                    uint2 u0 = inh[(size_t)s0 * 32 + lane];
                    uint2 u1 = inh[(size_t)s1 * 32 + lane];
                    uint2 u2 = inh[(size_t)s2 * 32 + lane];
                    uint2 u3 = inh[(size_t)s3 * 32 + lane];
                    float2 a0 = __half22float2(*(const __half2*)&u0.x);
                    float2 b0 = __half22float2(*(const __half2*)&u0.y);
                    float2 a1 = __half22float2(*(const __half2*)&u1.x);
                    float2 b1 = __half22float2(*(const __half2*)&u1.y);
                    float2 a2 = __half22float2(*(const __half2*)&u2.x);
                    float2 b2 = __half22float2(*(const __half2*)&u2.y);
                    float2 a3 = __half22float2(*(const __half2*)&u3.x);
                    float2 b3 = __half22float2(*(const __half2*)&u3.y);
                    acc.x += a0.x + a1.x + a2.x + a3.x;
                    acc.y += a0.y + a1.y + a2.y + a3.y;
                    acc.z += b0.x + b1.x + b2.x + b3.x;
                    acc.w += b0.y + b1.y + b2.y + b3.y;
                }
                for (; j < e; j++) {
                    int s0 = g_adj[j];
                    uint2 u0 = inh[(size_t)s0 * 32 + lane];
                    float2 a0 = __half22float2(*(const __half2*)&u0.x);
                    float2 b0 = __half22float2(*(const __half2*)&u0.y);
                    acc.x += a0.x; acc.y += a0.y; acc.z += b0.x; acc.w += b0.y;
                }
                acc.x *= di; acc.y *= di; acc.z *= di; acc.w *= di;
            }
        }
        int c = lane * 4;
        At[c + 0][nd] = acc.x;
        At[c + 1][nd] = acc.y;
        At[c + 2][nd] = acc.z;
        At[c + 3][nd] = acc.w;
    }
    if (POOL && tid < TM) rowsum[tid] = 0.f;

    // ---- phase 2: GEMM C[64x128] = At^T @ W, W staged in smem slabs ----
    int tx = tid & 15;              // rows tx*4 .. tx*4+3
    int ty = tid >> 4;              // cols ty*8 .. ty*8+7
    float acc[4][8];
#pragma unroll
    for (int r = 0; r < 4; r++)
#pragma unroll
        for (int j = 0; j < 8; j++) acc[r][j] = 0.f;

    for (int kb = 0; kb < D; kb += 16) {
#pragma unroll
        for (int l = 0; l < 2; l++) {
            int idx4 = tid + l * 256;
            int k = idx4 >> 5, c4 = idx4 & 31;
            *(float4*)&Ws[k][c4 * 4] = *(const float4*)&W[(size_t)(kb + k) * D + c4 * 4];
        }
        __syncthreads();
#pragma unroll
        for (int k = 0; k < 16; k++) {
            float a[4], b[8];
#pragma unroll
            for (int r = 0; r < 4; r++) a[r] = At[kb + k][tx * 4 + r];
            *(float4*)&b[0] = *(float4*)&Ws[k][ty * 8];
            *(float4*)&b[4] = *(float4*)&Ws[k][ty * 8 + 4];
#pragma unroll
            for (int r = 0; r < 4; r++)
#pragma unroll
                for (int j = 0; j < 8; j++) acc[r][j] += a[r] * b[j];
        }
        __syncthreads();
    }

    // ---- phase 3: epilogue ----
    if (!POOL) {
        uint4* houth = (uint4*)hout;        // fp16 h2, 8 halves per uint4, 16 per row
#pragma unroll
        for (int r = 0; r < 4; r++) {
            int row = row0 + tx * 4 + r;
            if (row < n) {
                float dr = g_dis[row];
                float v0 = dr * leaky(acc[r][0] + bias[ty * 8 + 0]);
                float v1 = dr * leaky(acc[r][1] + bias[ty * 8 + 1]);
                float v2 = dr * leaky(acc[r][2] + bias[ty * 8 + 2]);
                float v3 = dr * leaky(acc[r][3] + bias[ty * 8 + 3]);
                float v4 = dr * leaky(acc[r][4] + bias[ty * 8 + 4]);
                float v5 = dr * leaky(acc[r][5] + bias[ty * 8 + 5]);
                float v6 = dr * leaky(acc[r][6] + bias[ty * 8 + 6]);
                float v7 = dr * leaky(acc[r][7] + bias[ty * 8 + 7]);
                __half2 h0 = __floats2half2_rn(v0, v1);
                __half2 h1 = __floats2half2_rn(v2, v3);
                __half2 h2 = __floats2half2_rn(v4, v5);
                __half2 h3 = __floats2half2_rn(v6, v7);
                uint4 o;
                o.x = *(unsigned*)&h0; o.y = *(unsigned*)&h1;
                o.z = *(unsigned*)&h2; o.w = *(unsigned*)&h3;
                houth[(size_t)row * 16 + ty] = o;
            }
        }
    } else {
        float fj[8], bj[8];
#pragma unroll
        for (int j = 0; j < 8; j++) { fj[j] = fcW[ty * 8 + j]; bj[j] = bias[ty * 8 + j]; }
#pragma unroll
        for (int r = 0; r < 4; r++) {
            float s = 0.f;
#pragma unroll
            for (int j = 0; j < 8; j++) s += leaky(acc[r][j] + bj[j]) * fj[j];
            atomicAdd(&rowsum[tx * 4 + r], s);
        }
        __syncthreads();
        if (tid < TM) {
            int row = row0 + tid;
            if (row < n) {
                int g = idx_at(batch, row, g_is64);
                atomicAdd(&g_gsum[g * REP + (blockIdx.x & (REP - 1))], rowsum[tid]);
            }
        }
    }
}

// ---------------- final ----------------
__global__ void k_final(const void* __restrict__ batch, const float* __restrict__ fcb,
                        float* __restrict__ out, int n) {
    __shared__ int lb[G + 1];
    int is64 = g_is64;
    int t = threadIdx.x;
    if (t <= G) {
        int lo = 0, hi = n;
        while (lo < hi) {
            int mid = (lo + hi) >> 1;
            if (idx_at(batch, mid, is64) < t) lo = mid + 1; else hi = mid;
        }
        lb[t] = lo;
    }
    __syncthreads();
    if (t < G) {
        float s = 0.f;
#pragma unroll
        for (int r = 0; r < REP; r++) s += g_gsum[t * REP + r];
        float c = (float)(lb[t + 1] - lb[t]);
        if (c < 1.f) c = 1.f;
        out[t] = s / c + fcb[0];
    }
}

// ---------------- launch ----------------
extern "C" void kernel_launch(void* const* d_in, const int* in_sizes, int n_in,
                              void* d_out, int out_size) {
    const float* x    = (const float*)d_in[0];
    const void*  ei   = d_in[1];
    const void*  bat  = d_in[2];
    const float* W1   = (const float*)d_in[3];
    const float* b1   = (const float*)d_in[4];
    const float* W2   = (const float*)d_in[5];
    const float* b2   = (const float*)d_in[6];
    const float* fcW  = (const float*)d_in[7];
    const float* fcb  = (const float*)d_in[8];
    float*       out  = (float*)d_out;

    int n = in_sizes[0] / D;
    int e = in_sizes[1] / 2;
    int nb = (n + SCB - 1) / SCB;

    void *h2, *degp, *gsump;
    cudaGetSymbolAddress(&h2, g_h2);
    cudaGetSymbolAddress(&degp, g_deg);
    cudaGetSymbolAddress(&gsump, g_gsum);

    int tb = 256;
    // CSR build (deg/gsum zeroed via memset nodes; no k_init kernel)
    cudaMemsetAsync(degp, 0, (size_t)n * sizeof(int), 0);
    cudaMemsetAsync(gsump, 0, (size_t)G * REP * sizeof(float), 0);
    k_deg<<<(e + tb - 1) / tb, tb>>>(ei, e);
    k_scanA<<<nb, SCB>>>((const int*)ei, n);
    k_scanB<<<nb, SCB>>>(nb, n);
    k_fill<<<(e + tb - 1) / tb, tb>>>(ei, e);

    int gblk = (n + TM - 1) / TM;
    // layer 1: h2(fp16) = dis .* leaky(agg(x)@W1 + b1)   (weighted gather)
    k_fused<0, 1><<<gblk, 256>>>(x, W1, b1, nullptr, nullptr, h2, n);
    // layer 2 + pool/fc (pure-sum gather over pre-scaled fp16 h2)
    k_fused<1, 0><<<gblk, 256>>>(h2, W2, b2, fcW, bat, nullptr, n);

    k_final<<<1, 128>>>(bat, fcb, out, n);
}

// round 15
// speedup vs baseline: 1.1957x; 1.0469x over previous
#include <cuda_runtime.h>
#include <cuda_fp16.h>
#include <cstdint>

#define MAXN 100000
#define MAXE 1600000
#define D    128
#define G    64
#define REP  32
#define SCB  1024
#define TM   64      // nodes per fused-kernel block

// ---------------- device scratch ----------------
__device__ __half g_xh[MAXN * D];       // fp16 pre-scaled input: dis_i * x_i
__device__ __half g_h2[MAXN * D];       // fp16 pre-scaled layer-1 activation
__device__ int   g_deg[MAXN];           // in-degree (memset to 0)
__device__ float g_dis[MAXN];
__device__ int   g_off[MAXN + 1];
__device__ int   g_cursor[MAXN];
__device__ int   g_adj[MAXE];           // src index (only CSR payload)
__device__ float g_gsum[G * REP];       // memset to 0
__device__ int   g_bsum[128];
__device__ int   g_is64;

// ---------------- dtype-agnostic index read ----------------
__device__ __forceinline__ int idx_at(const void* p, size_t i, int is64) {
    if (is64) return (int)((const long long*)p)[i];
    return ((const int*)p)[i];
}

__device__ __forceinline__ int detect64(const int* w) {
    int allz = 1;
    for (int j = 1; j < 32; j += 2)
        if (w[j] != 0) allz = 0;
    return allz;
}

// ---------------- in-degree count (per-block dtype detect) ----------------
__global__ void k_deg(const void* __restrict__ ei, int e) {
    __shared__ int s64;
    if (threadIdx.x == 0) s64 = detect64((const int*)ei);
    __syncthreads();
    int i = blockIdx.x * blockDim.x + threadIdx.x;
    if (i < e) atomicAdd(&g_deg[idx_at(ei, (size_t)e + i, s64)], 1);
}

// ---------------- scanA: block sums of deg; dis=rsqrt(deg+1); publish g_is64 ----------------
__global__ void k_scanA(const int* __restrict__ ei32, int n) {
    if (blockIdx.x == 0 && threadIdx.x == 0) g_is64 = detect64(ei32);
    int i = blockIdx.x * SCB + threadIdx.x;
    int v = 0;
    if (i < n) {
        int d = g_deg[i];
        g_dis[i] = rsqrtf((float)(d + 1));
        v = d;
    }
    int s = v;
#pragma unroll
    for (int o = 16; o; o >>= 1) s += __shfl_down_sync(0xffffffffu, s, o);
    __shared__ int ws[SCB / 32];
    int w = threadIdx.x >> 5, l = threadIdx.x & 31;
    if (l == 0) ws[w] = s;
    __syncthreads();
    if (w == 0) {
        int t = (l < SCB / 32) ? ws[l] : 0;
#pragma unroll
        for (int o = 16; o; o >>= 1) t += __shfl_down_sync(0xffffffffu, t, o);
        if (l == 0) g_bsum[blockIdx.x] = t;
    }
}

// ---------------- prescale: xh = fp16(dis .* x)  (runs on forked stream) ----------------
__global__ void k_prescale(const float4* __restrict__ x, uint2* __restrict__ xh, int n4) {
    int i = blockIdx.x * blockDim.x + threadIdx.x;
    if (i < n4) {
        float d = g_dis[i >> 5];
        float4 v = x[i];
        __half2 h0 = __floats2half2_rn(v.x * d, v.y * d);
        __half2 h1 = __floats2half2_rn(v.z * d, v.w * d);
        uint2 o;
        o.x = *(unsigned*)&h0;
        o.y = *(unsigned*)&h1;
        xh[i] = o;
    }
}

// ---------------- scanB: redundant block-sum scan + per-element offsets + cursor ----------------
__global__ void k_scanB(int nb, int n) {
    __shared__ int sm[128];
    __shared__ int ws[SCB / 32];
    int t = threadIdx.x;
    if (t < 128) sm[t] = (t < nb) ? g_bsum[t] : 0;
    __syncthreads();
    for (int o = 1; o < 128; o <<= 1) {
        int u = (t >= o && t < 128) ? sm[t - o] : 0;
        __syncthreads();
        if (t >= o && t < 128) sm[t] += u;
        __syncthreads();
    }
    int bbase = sm[blockIdx.x] - g_bsum[blockIdx.x];
    if (blockIdx.x == 0 && t == 0) g_off[n] = sm[127];

    int i = blockIdx.x * SCB + t;
    int v = (i < n) ? g_deg[i] : 0;
    int incl = v;
#pragma unroll
    for (int o = 1; o < 32; o <<= 1) {
        int u = __shfl_up_sync(0xffffffffu, incl, o);
        if ((t & 31) >= o) incl += u;
    }
    int w = t >> 5, l = t & 31;
    if (l == 31) ws[w] = incl;
    __syncthreads();
    if (w == 0) {
        int s = (l < SCB / 32) ? ws[l] : 0;
        int si = s;
#pragma unroll
        for (int o = 1; o < 32; o <<= 1) {
            int u = __shfl_up_sync(0xffffffffu, si, o);
            if (l >= o) si += u;
        }
        ws[l] = si - s;
    }
    __syncthreads();
    if (i < n) {
        int off = bbase + ws[w] + (incl - v);
        g_off[i] = off;
        g_cursor[i] = off;
    }
}

// ---------------- fill CSR (adj only) ----------------
__global__ void k_fill(const void* __restrict__ ei, int e) {
    int is64 = g_is64;
    int i = blockIdx.x * blockDim.x + threadIdx.x;
    if (i < e) {
        int r = idx_at(ei, i, is64);
        int c = idx_at(ei, (size_t)e + i, is64);
        int pos = atomicAdd(&g_cursor[c], 1);
        g_adj[pos] = r;
    }
}

// ---------------- fused layer: weightless fp16 gather -> smem -> FFMA GEMM -> epilogue ----------------
// input pre-scaled by dis_j, so agg_i = dis_i * (sum_j in_j + in_i)
__device__ __forceinline__ float leaky(float x) { return x >= 0.f ? x : 0.01f * x; }

template <int POOL>
__global__ __launch_bounds__(256, 4) void k_fused(
    const uint2* __restrict__ in, const float* __restrict__ W,
    const float* __restrict__ bias, const float* __restrict__ fcW,
    const void* __restrict__ batch, void* __restrict__ hout, int n)
{
    __shared__ float At[D][66];     // feature-major agg tile
    __shared__ float Ws[16][D];
    __shared__ float rowsum[TM];

    int tid = threadIdx.x;
    int warp = tid >> 5, lane = tid & 31;
    int row0 = blockIdx.x * TM;

    // ---- phase 1: gather (warp per node, lane = feature quad), 4-wide MLP ----
    for (int nd = warp; nd < TM; nd += 8) {
        int node = row0 + nd;
        float4 acc = make_float4(0.f, 0.f, 0.f, 0.f);
        if (node < n) {
            float di = g_dis[node];
            uint2 u = in[(size_t)node * 32 + lane];
            float2 f0 = __half22float2(*(const __half2*)&u.x);
            float2 f1 = __half22float2(*(const __half2*)&u.y);
            acc.x = f0.x; acc.y = f0.y; acc.z = f1.x; acc.w = f1.y;
            int s = g_off[node], e = g_off[node + 1];
            int j = s;
            for (; j + 4 <= e; j += 4) {
                int s0 = g_adj[j], s1 = g_adj[j + 1], s2 = g_adj[j + 2], s3 = g_adj[j + 3];
                uint2 u0 = in[(size_t)s0 * 32 + lane];
                uint2 u1 = in[(size_t)s1 * 32 + lane];
                uint2 u2 = in[(size_t)s2 * 32 + lane];
                uint2 u3 = in[(size_t)s3 * 32 + lane];
                float2 a0 = __half22float2(*(const __half2*)&u0.x);
                float2 b0 = __half22float2(*(const __half2*)&u0.y);
                float2 a1 = __half22float2(*(const __half2*)&u1.x);
                float2 b1 = __half22float2(*(const __half2*)&u1.y);
                float2 a2 = __half22float2(*(const __half2*)&u2.x);
                float2 b2 = __half22float2(*(const __half2*)&u2.y);
                float2 a3 = __half22float2(*(const __half2*)&u3.x);
                float2 b3 = __half22float2(*(const __half2*)&u3.y);
                acc.x += a0.x + a1.x + a2.x + a3.x;
                acc.y += a0.y + a1.y + a2.y + a3.y;
                acc.z += b0.x + b1.x + b2.x + b3.x;
                acc.w += b0.y + b1.y + b2.y + b3.y;
            }
            for (; j < e; j++) {
                int s0 = g_adj[j];
                uint2 u0 = in[(size_t)s0 * 32 + lane];
                float2 a0 = __half22float2(*(const __half2*)&u0.x);
                float2 b0 = __half22float2(*(const __half2*)&u0.y);
                acc.x += a0.x; acc.y += a0.y; acc.z += b0.x; acc.w += b0.y;
            }
            acc.x *= di; acc.y *= di; acc.z *= di; acc.w *= di;
        }
        int c = lane * 4;
        At[c + 0][nd] = acc.x;
        At[c + 1][nd] = acc.y;
        At[c + 2][nd] = acc.z;
        At[c + 3][nd] = acc.w;
    }
    if (POOL && tid < TM) rowsum[tid] = 0.f;

    // ---- phase 2: GEMM C[64x128] = At^T @ W, W staged in smem slabs ----
    int tx = tid & 15;
    int ty = tid >> 4;
    float acc[4][8];
#pragma unroll
    for (int r = 0; r < 4; r++)
#pragma unroll
        for (int j = 0; j < 8; j++) acc[r][j] = 0.f;

    for (int kb = 0; kb < D; kb += 16) {
#pragma unroll
        for (int l = 0; l < 2; l++) {
            int idx4 = tid + l * 256;
            int k = idx4 >> 5, c4 = idx4 & 31;
            *(float4*)&Ws[k][c4 * 4] = *(const float4*)&W[(size_t)(kb + k) * D + c4 * 4];
        }
        __syncthreads();
#pragma unroll
        for (int k = 0; k < 16; k++) {
            float a[4], b[8];
#pragma unroll
            for (int r = 0; r < 4; r++) a[r] = At[kb + k][tx * 4 + r];
            *(float4*)&b[0] = *(float4*)&Ws[k][ty * 8];
            *(float4*)&b[4] = *(float4*)&Ws[k][ty * 8 + 4];
#pragma unroll
            for (int r = 0; r < 4; r++)
#pragma unroll
                for (int j = 0; j < 8; j++) acc[r][j] += a[r] * b[j];
        }
        __syncthreads();
    }

    // ---- phase 3: epilogue ----
    if (!POOL) {
        uint4* houth = (uint4*)hout;        // fp16 h2, 8 halves per uint4
#pragma unroll
        for (int r = 0; r < 4; r++) {
            int row = row0 + tx * 4 + r;
            if (row < n) {
                float dr = g_dis[row];
                float v0 = dr * leaky(acc[r][0] + bias[ty * 8 + 0]);
                float v1 = dr * leaky(acc[r][1] + bias[ty * 8 + 1]);
                float v2 = dr * leaky(acc[r][2] + bias[ty * 8 + 2]);
                float v3 = dr * leaky(acc[r][3] + bias[ty * 8 + 3]);
                float v4 = dr * leaky(acc[r][4] + bias[ty * 8 + 4]);
                float v5 = dr * leaky(acc[r][5] + bias[ty * 8 + 5]);
                float v6 = dr * leaky(acc[r][6] + bias[ty * 8 + 6]);
                float v7 = dr * leaky(acc[r][7] + bias[ty * 8 + 7]);
                __half2 h0 = __floats2half2_rn(v0, v1);
                __half2 h1 = __floats2half2_rn(v2, v3);
                __half2 h2 = __floats2half2_rn(v4, v5);
                __half2 h3 = __floats2half2_rn(v6, v7);
                uint4 o;
                o.x = *(unsigned*)&h0; o.y = *(unsigned*)&h1;
                o.z = *(unsigned*)&h2; o.w = *(unsigned*)&h3;
                houth[(size_t)row * 16 + ty] = o;
            }
        }
    } else {
        float fj[8], bj[8];
#pragma unroll
        for (int j = 0; j < 8; j++) { fj[j] = fcW[ty * 8 + j]; bj[j] = bias[ty * 8 + j]; }
#pragma unroll
        for (int r = 0; r < 4; r++) {
            float s = 0.f;
#pragma unroll
            for (int j = 0; j < 8; j++) s += leaky(acc[r][j] + bj[j]) * fj[j];
            atomicAdd(&rowsum[tx * 4 + r], s);
        }
        __syncthreads();
        if (tid < TM) {
            int row = row0 + tid;
            if (row < n) {
                int g = idx_at(batch, row, g_is64);
                atomicAdd(&g_gsum[g * REP + (blockIdx.x & (REP - 1))], rowsum[tid]);
            }
        }
    }
}

// ---------------- final ----------------
__global__ void k_final(const void* __restrict__ batch, const float* __restrict__ fcb,
                        float* __restrict__ out, int n) {
    __shared__ int lb[G + 1];
    int is64 = g_is64;
    int t = threadIdx.x;
    if (t <= G) {
        int lo = 0, hi = n;
        while (lo < hi) {
            int mid = (lo + hi) >> 1;
            if (idx_at(batch, mid, is64) < t) lo = mid + 1; else hi = mid;
        }
        lb[t] = lo;
    }
    __syncthreads();
    if (t < G) {
        float s = 0.f;
#pragma unroll
        for (int r = 0; r < REP; r++) s += g_gsum[t * REP + r];
        float c = (float)(lb[t + 1] - lb[t]);
        if (c < 1.f) c = 1.f;
        out[t] = s / c + fcb[0];
    }
}

// ---------------- launch ----------------
extern "C" void kernel_launch(void* const* d_in, const int* in_sizes, int n_in,
                              void* d_out, int out_size) {
    const float* x    = (const float*)d_in[0];
    const void*  ei   = d_in[1];
    const void*  bat  = d_in[2];
    const float* W1   = (const float*)d_in[3];
    const float* b1   = (const float*)d_in[4];
    const float* W2   = (const float*)d_in[5];
    const float* b2   = (const float*)d_in[6];
    const float* fcW  = (const float*)d_in[7];
    const float* fcb  = (const float*)d_in[8];
    float*       out  = (float*)d_out;

    int n = in_sizes[0] / D;
    int e = in_sizes[1] / 2;
    int nb = (n + SCB - 1) / SCB;

    void *xh, *h2, *degp, *gsump;
    cudaGetSymbolAddress(&xh, g_xh);
    cudaGetSymbolAddress(&h2, g_h2);
    cudaGetSymbolAddress(&degp, g_deg);
    cudaGetSymbolAddress(&gsump, g_gsum);

    static cudaStream_t s2 = nullptr;
    static cudaEvent_t ev_dis = nullptr, ev_xh = nullptr;
    if (!s2) {
        cudaStreamCreateWithFlags(&s2, cudaStreamNonBlocking);
        cudaEventCreateWithFlags(&ev_dis, cudaEventDisableTiming);
        cudaEventCreateWithFlags(&ev_xh, cudaEventDisableTiming);
    }

    int tb = 256;
    // CSR build
    cudaMemsetAsync(degp, 0, (size_t)n * sizeof(int), 0);
    cudaMemsetAsync(gsump, 0, (size_t)G * REP * sizeof(float), 0);
    k_deg<<<(e + tb - 1) / tb, tb>>>(ei, e);
    k_scanA<<<nb, SCB>>>((const int*)ei, n);
    cudaEventRecord(ev_dis, 0);

    // fork: prescale xh = fp16(dis .* x) overlaps scanB + fill
    cudaStreamWaitEvent(s2, ev_dis, 0);
    int n4 = n * 32;
    k_prescale<<<(n4 + tb - 1) / tb, tb, 0, s2>>>((const float4*)x, (uint2*)xh, n4);
    cudaEventRecord(ev_xh, s2);

    k_scanB<<<nb, SCB>>>(nb, n);
    k_fill<<<(e + tb - 1) / tb, tb>>>(ei, e);

    cudaStreamWaitEvent(0, ev_xh, 0);
    int gblk = (n + TM - 1) / TM;
    // layer 1: h2(fp16) = dis .* leaky(dis.*(sum xh)@W1 + b1)
    k_fused<0><<<gblk, 256>>>((const uint2*)xh, W1, b1, nullptr, nullptr, h2, n);
    // layer 2 + pool/fc
    k_fused<1><<<gblk, 256>>>((const uint2*)h2, W2, b2, fcW, bat, nullptr, n);

    k_final<<<1, 128>>>(bat, fcb, out, n);
}

// round 16
// speedup vs baseline: 1.9474x; 1.6288x over previous
#include <cuda_runtime.h>
#include <cuda_fp16.h>
#include <cstdint>

#define MAXN 100000
#define MAXE 1600000
#define D    128
#define G    64
#define REP  32
#define SCB  1024
#define TM   64      // nodes per fused-kernel block
#define PADH 136     // At pitch in halves: 272B -> 4-bank row shift, ldmatrix conflict-free

// ---------------- device scratch ----------------
__device__ __half g_xh[MAXN * D];       // fp16 pre-scaled input: dis_i * x_i
__device__ __half g_h2[MAXN * D];       // fp16 pre-scaled layer-1 activation
__device__ uint2  g_whf[2 * 4096];      // fp16 W1/W2 in m16n8k16 B-fragment order
__device__ int    g_deg[MAXN];
__device__ float  g_dis[MAXN];
__device__ int    g_off[MAXN + 1];
__device__ int    g_cursor[MAXN];
__device__ int    g_adj[MAXE];
__device__ float  g_gsum[G * REP];
__device__ int    g_bsum[128];
__device__ int    g_is64;

// ---------------- dtype-agnostic index read ----------------
__device__ __forceinline__ int idx_at(const void* p, size_t i, int is64) {
    if (is64) return (int)((const long long*)p)[i];
    return ((const int*)p)[i];
}

__device__ __forceinline__ int detect64(const int* w) {
    int allz = 1;
    for (int j = 1; j < 32; j += 2)
        if (w[j] != 0) allz = 0;
    return allz;
}

// ---------------- W prep: fp16 + permute to m16n8k16 B-fragment order ----------------
// slot = (ks*16 + ntile)*32 + lane ; lane = g*4+tig
// .x = half2(W[ks*16+2tig  ][ntile*8+g], W[ks*16+2tig+1][ntile*8+g])
// .y = half2(W[ks*16+2tig+8][ntile*8+g], W[ks*16+2tig+9][ntile*8+g])
__global__ void k_wprep(const float* __restrict__ W1, const float* __restrict__ W2) {
    int i = blockIdx.x * blockDim.x + threadIdx.x;   // 0..8191
    int l = i >> 12;
    int r = i & 4095;
    int lane = r & 31;
    int nt = (r >> 5) & 15;
    int ks = r >> 9;
    int g = lane >> 2, tig = lane & 3;
    const float* W = l ? W2 : W1;
    int nn = nt * 8 + g;
    int k0 = ks * 16 + 2 * tig;
    __half2 x = __floats2half2_rn(W[k0 * D + nn], W[(k0 + 1) * D + nn]);
    __half2 y = __floats2half2_rn(W[(k0 + 8) * D + nn], W[(k0 + 9) * D + nn]);
    uint2 o;
    o.x = *(unsigned*)&x;
    o.y = *(unsigned*)&y;
    g_whf[i] = o;
}

// ---------------- in-degree count (per-block dtype detect) ----------------
__global__ void k_deg(const void* __restrict__ ei, int e) {
    __shared__ int s64;
    if (threadIdx.x == 0) s64 = detect64((const int*)ei);
    __syncthreads();
    int i = blockIdx.x * blockDim.x + threadIdx.x;
    if (i < e) atomicAdd(&g_deg[idx_at(ei, (size_t)e + i, s64)], 1);
}

// ---------------- scanA: block sums of deg; dis=rsqrt(deg+1); publish g_is64 ----------------
__global__ void k_scanA(const int* __restrict__ ei32, int n) {
    if (blockIdx.x == 0 && threadIdx.x == 0) g_is64 = detect64(ei32);
    int i = blockIdx.x * SCB + threadIdx.x;
    int v = 0;
    if (i < n) {
        int d = g_deg[i];
        g_dis[i] = rsqrtf((float)(d + 1));
        v = d;
    }
    int s = v;
#pragma unroll
    for (int o = 16; o; o >>= 1) s += __shfl_down_sync(0xffffffffu, s, o);
    __shared__ int ws[SCB / 32];
    int w = threadIdx.x >> 5, l = threadIdx.x & 31;
    if (l == 0) ws[w] = s;
    __syncthreads();
    if (w == 0) {
        int t = (l < SCB / 32) ? ws[l] : 0;
#pragma unroll
        for (int o = 16; o; o >>= 1) t += __shfl_down_sync(0xffffffffu, t, o);
        if (l == 0) g_bsum[blockIdx.x] = t;
    }
}

// ---------------- prescale: xh = fp16(dis .* x)  (forked stream) ----------------
__global__ void k_prescale(const float4* __restrict__ x, uint2* __restrict__ xh, int n4) {
    int i = blockIdx.x * blockDim.x + threadIdx.x;
    if (i < n4) {
        float d = g_dis[i >> 5];
        float4 v = x[i];
        __half2 h0 = __floats2half2_rn(v.x * d, v.y * d);
        __half2 h1 = __floats2half2_rn(v.z * d, v.w * d);
        uint2 o;
        o.x = *(unsigned*)&h0;
        o.y = *(unsigned*)&h1;
        xh[i] = o;
    }
}

// ---------------- scanB: redundant block-sum scan + offsets + cursor ----------------
__global__ void k_scanB(int nb, int n) {
    __shared__ int sm[128];
    __shared__ int ws[SCB / 32];
    int t = threadIdx.x;
    if (t < 128) sm[t] = (t < nb) ? g_bsum[t] : 0;
    __syncthreads();
    for (int o = 1; o < 128; o <<= 1) {
        int u = (t >= o && t < 128) ? sm[t - o] : 0;
        __syncthreads();
        if (t >= o && t < 128) sm[t] += u;
        __syncthreads();
    }
    int bbase = sm[blockIdx.x] - g_bsum[blockIdx.x];
    if (blockIdx.x == 0 && t == 0) g_off[n] = sm[127];

    int i = blockIdx.x * SCB + t;
    int v = (i < n) ? g_deg[i] : 0;
    int incl = v;
#pragma unroll
    for (int o = 1; o < 32; o <<= 1) {
        int u = __shfl_up_sync(0xffffffffu, incl, o);
        if ((t & 31) >= o) incl += u;
    }
    int w = t >> 5, l = t & 31;
    if (l == 31) ws[w] = incl;
    __syncthreads();
    if (w == 0) {
        int s = (l < SCB / 32) ? ws[l] : 0;
        int si = s;
#pragma unroll
        for (int o = 1; o < 32; o <<= 1) {
            int u = __shfl_up_sync(0xffffffffu, si, o);
            if (l >= o) si += u;
        }
        ws[l] = si - s;
    }
    __syncthreads();
    if (i < n) {
        int off = bbase + ws[w] + (incl - v);
        g_off[i] = off;
        g_cursor[i] = off;
    }
}

// ---------------- fill CSR (adj only) ----------------
__global__ void k_fill(const void* __restrict__ ei, int e) {
    int is64 = g_is64;
    int i = blockIdx.x * blockDim.x + threadIdx.x;
    if (i < e) {
        int r = idx_at(ei, i, is64);
        int c = idx_at(ei, (size_t)e + i, is64);
        int pos = atomicAdd(&g_cursor[c], 1);
        g_adj[pos] = r;
    }
}

// ---------------- fused layer: fp16 gather -> smem -> HMMA tensor GEMM -> epilogue ----------------
__device__ __forceinline__ float leaky(float x) { return x >= 0.f ? x : 0.01f * x; }

template <int POOL>
__global__ __launch_bounds__(256, 4) void k_fused(
    const uint2* __restrict__ in, const uint2* __restrict__ whf,
    const float* __restrict__ bias, const float* __restrict__ fcW,
    const void* __restrict__ batch, void* __restrict__ hout, int n)
{
    __shared__ __half At[TM][PADH];     // node-major fp16 agg tile
    __shared__ float rowsum[TM];

    int tid = threadIdx.x;
    int warp = tid >> 5, lane = tid & 31;
    int row0 = blockIdx.x * TM;

    // ---- phase 1: gather (warp per node, lane = feature quad), 4-wide MLP ----
    for (int nd = warp; nd < TM; nd += 8) {
        int node = row0 + nd;
        float4 acc = make_float4(0.f, 0.f, 0.f, 0.f);
        if (node < n) {
            float di = g_dis[node];
            uint2 u = in[(size_t)node * 32 + lane];
            float2 f0 = __half22float2(*(const __half2*)&u.x);
            float2 f1 = __half22float2(*(const __half2*)&u.y);
            acc.x = f0.x; acc.y = f0.y; acc.z = f1.x; acc.w = f1.y;
            int s = g_off[node], e = g_off[node + 1];
            int j = s;
            for (; j + 4 <= e; j += 4) {
                int s0 = g_adj[j], s1 = g_adj[j + 1], s2 = g_adj[j + 2], s3 = g_adj[j + 3];
                uint2 u0 = in[(size_t)s0 * 32 + lane];
                uint2 u1 = in[(size_t)s1 * 32 + lane];
                uint2 u2 = in[(size_t)s2 * 32 + lane];
                uint2 u3 = in[(size_t)s3 * 32 + lane];
                float2 a0 = __half22float2(*(const __half2*)&u0.x);
                float2 b0 = __half22float2(*(const __half2*)&u0.y);
                float2 a1 = __half22float2(*(const __half2*)&u1.x);
                float2 b1 = __half22float2(*(const __half2*)&u1.y);
                float2 a2 = __half22float2(*(const __half2*)&u2.x);
                float2 b2 = __half22float2(*(const __half2*)&u2.y);
                float2 a3 = __half22float2(*(const __half2*)&u3.x);
                float2 b3 = __half22float2(*(const __half2*)&u3.y);
                acc.x += a0.x + a1.x + a2.x + a3.x;
                acc.y += a0.y + a1.y + a2.y + a3.y;
                acc.z += b0.x + b1.x + b2.x + b3.x;
                acc.w += b0.y + b1.y + b2.y + b3.y;
            }
            for (; j < e; j++) {
                int s0 = g_adj[j];
                uint2 u0 = in[(size_t)s0 * 32 + lane];
                float2 a0 = __half22float2(*(const __half2*)&u0.x);
                float2 b0 = __half22float2(*(const __half2*)&u0.y);
                acc.x += a0.x; acc.y += a0.y; acc.z += b0.x; acc.w += b0.y;
            }
            acc.x *= di; acc.y *= di; acc.z *= di; acc.w *= di;
        }
        __half2 h0 = __floats2half2_rn(acc.x, acc.y);
        __half2 h1 = __floats2half2_rn(acc.z, acc.w);
        uint2 st;
        st.x = *(unsigned*)&h0;
        st.y = *(unsigned*)&h1;
        *(uint2*)&At[nd][lane * 4] = st;
    }
    if (POOL && tid < TM) rowsum[tid] = 0.f;
    __syncthreads();

    // ---- phase 2: tensor-core GEMM C[64x128] = At @ W (m16n8k16 fp16, fp32 accum) ----
    int g = lane >> 2, tig = lane & 3;
    int m0 = (warp & 3) * 16;           // 16-node strip
    int nb0 = (warp >> 2) * 8;          // 8 n-tiles (64 cols)
    uint32_t at_base = (uint32_t)__cvta_generic_to_shared(&At[0][0]);
    int tt = lane >> 3, rr = lane & 7;
    uint32_t arow = at_base +
        (uint32_t)(((m0 + (tt & 1) * 8 + rr) * PADH + (tt >> 1) * 8) * 2);

    float c[8][4];
#pragma unroll
    for (int nt = 0; nt < 8; nt++)
#pragma unroll
        for (int q = 0; q < 4; q++) c[nt][q] = 0.f;

#pragma unroll
    for (int ks = 0; ks < 8; ks++) {
        uint32_t a0, a1, a2, a3;
        asm volatile(
            "ldmatrix.sync.aligned.m8n8.x4.shared.b16 {%0,%1,%2,%3}, [%4];"
            : "=r"(a0), "=r"(a1), "=r"(a2), "=r"(a3)
            : "r"(arow + (uint32_t)(ks * 32)));
#pragma unroll
        for (int nt = 0; nt < 8; nt++) {
            uint2 b = __ldg(&whf[(ks * 16 + nb0 + nt) * 32 + lane]);
            asm volatile(
                "mma.sync.aligned.m16n8k16.row.col.f32.f16.f16.f32 "
                "{%0,%1,%2,%3}, {%4,%5,%6,%7}, {%8,%9}, {%0,%1,%2,%3};"
                : "+f"(c[nt][0]), "+f"(c[nt][1]), "+f"(c[nt][2]), "+f"(c[nt][3])
                : "r"(a0), "r"(a1), "r"(a2), "r"(a3), "r"(b.x), "r"(b.y));
        }
    }

    // ---- phase 3: epilogue (thread owns rows m0+g, m0+g+8; cols (nb0+nt)*8+2tig..+1) ----
    int r0g = row0 + m0 + g;
    int r1g = r0g + 8;
    if (!POOL) {
        __half* hh = (__half*)hout;
        float d0 = (r0g < n) ? g_dis[r0g] : 0.f;
        float d1 = (r1g < n) ? g_dis[r1g] : 0.f;
#pragma unroll
        for (int nt = 0; nt < 8; nt++) {
            int col = (nb0 + nt) * 8 + 2 * tig;
            float b0 = bias[col], b1 = bias[col + 1];
            if (r0g < n) {
                __half2 h = __floats2half2_rn(d0 * leaky(c[nt][0] + b0),
                                              d0 * leaky(c[nt][1] + b1));
                *(__half2*)&hh[(size_t)r0g * D + col] = h;
            }
            if (r1g < n) {
                __half2 h = __floats2half2_rn(d1 * leaky(c[nt][2] + b0),
                                              d1 * leaky(c[nt][3] + b1));
                *(__half2*)&hh[(size_t)r1g * D + col] = h;
            }
        }
    } else {
        float p0 = 0.f, p1 = 0.f;
#pragma unroll
        for (int nt = 0; nt < 8; nt++) {
            int col = (nb0 + nt) * 8 + 2 * tig;
            float b0 = bias[col], b1 = bias[col + 1];
            float f0 = fcW[col], f1 = fcW[col + 1];
            p0 += leaky(c[nt][0] + b0) * f0 + leaky(c[nt][1] + b1) * f1;
            p1 += leaky(c[nt][2] + b0) * f0 + leaky(c[nt][3] + b1) * f1;
        }
        p0 += __shfl_xor_sync(0xffffffffu, p0, 1);
        p0 += __shfl_xor_sync(0xffffffffu, p0, 2);
        p1 += __shfl_xor_sync(0xffffffffu, p1, 1);
        p1 += __shfl_xor_sync(0xffffffffu, p1, 2);
        if (tig == 0) {
            atomicAdd(&rowsum[m0 + g], p0);
            atomicAdd(&rowsum[m0 + g + 8], p1);
        }
        __syncthreads();
        if (tid < TM) {
            int row = row0 + tid;
            if (row < n) {
                int gg = idx_at(batch, row, g_is64);
                atomicAdd(&g_gsum[gg * REP + (blockIdx.x & (REP - 1))], rowsum[tid]);
            }
        }
    }
}

// ---------------- final ----------------
__global__ void k_final(const void* __restrict__ batch, const float* __restrict__ fcb,
                        float* __restrict__ out, int n) {
    __shared__ int lb[G + 1];
    int is64 = g_is64;
    int t = threadIdx.x;
    if (t <= G) {
        int lo = 0, hi = n;
        while (lo < hi) {
            int mid = (lo + hi) >> 1;
            if (idx_at(batch, mid, is64) < t) lo = mid + 1; else hi = mid;
        }
        lb[t] = lo;
    }
    __syncthreads();
    if (t < G) {
        float s = 0.f;
#pragma unroll
        for (int r = 0; r < REP; r++) s += g_gsum[t * REP + r];
        float c = (float)(lb[t + 1] - lb[t]);
        if (c < 1.f) c = 1.f;
        out[t] = s / c + fcb[0];
    }
}

// ---------------- launch ----------------
extern "C" void kernel_launch(void* const* d_in, const int* in_sizes, int n_in,
                              void* d_out, int out_size) {
    const float* x    = (const float*)d_in[0];
    const void*  ei   = d_in[1];
    const void*  bat  = d_in[2];
    const float* W1   = (const float*)d_in[3];
    const float* b1   = (const float*)d_in[4];
    const float* W2   = (const float*)d_in[5];
    const float* b2   = (const float*)d_in[6];
    const float* fcW  = (const float*)d_in[7];
    const float* fcb  = (const float*)d_in[8];
    float*       out  = (float*)d_out;

    int n = in_sizes[0] / D;
    int e = in_sizes[1] / 2;
    int nb = (n + SCB - 1) / SCB;

    void *xh, *h2, *whf, *degp, *gsump;
    cudaGetSymbolAddress(&xh, g_xh);
    cudaGetSymbolAddress(&h2, g_h2);
    cudaGetSymbolAddress(&whf, g_whf);
    cudaGetSymbolAddress(&degp, g_deg);
    cudaGetSymbolAddress(&gsump, g_gsum);

    static cudaStream_t s2 = nullptr;
    static cudaEvent_t ev_dis = nullptr, ev_xh = nullptr;
    if (!s2) {
        cudaStreamCreateWithFlags(&s2, cudaStreamNonBlocking);
        cudaEventCreateWithFlags(&ev_dis, cudaEventDisableTiming);
        cudaEventCreateWithFlags(&ev_xh, cudaEventDisableTiming);
    }

    int tb = 256;
    // fork stream: W fragment prep (independent of CSR)
    k_wprep<<<32, 256, 0, s2>>>(W1, W2);

    // CSR build on main stream
    cudaMemsetAsync(degp, 0, (size_t)n * sizeof(int), 0);
    cudaMemsetAsync(gsump, 0, (size_t)G * REP * sizeof(float), 0);
    k_deg<<<(e + tb - 1) / tb, tb>>>(ei, e);
    k_scanA<<<nb, SCB>>>((const int*)ei, n);
    cudaEventRecord(ev_dis, 0);

    // fork: prescale xh = fp16(dis .* x), overlaps scanB + fill
    cudaStreamWaitEvent(s2, ev_dis, 0);
    int n4 = n * 32;
    k_prescale<<<(n4 + tb - 1) / tb, tb, 0, s2>>>((const float4*)x, (uint2*)xh, n4);
    cudaEventRecord(ev_xh, s2);

    k_scanB<<<nb, SCB>>>(nb, n);
    k_fill<<<(e + tb - 1) / tb, tb>>>(ei, e);

    cudaStreamWaitEvent(0, ev_xh, 0);
    int gblk = (n + TM - 1) / TM;
    // layer 1: h2(fp16) = dis .* leaky(dis.*(sum xh)@W1 + b1)
    k_fused<0><<<gblk, 256>>>((const uint2*)xh, (const uint2*)whf, b1, nullptr,
                              nullptr, h2, n);
    // layer 2 + pool/fc
    k_fused<1><<<gblk, 256>>>((const uint2*)h2, (const uint2*)whf + 4096, b2, fcW,
                              bat, nullptr, n);

    k_final<<<1, 128>>>(bat, fcb, out, n);
}